// round 11
// baseline (speedup 1.0000x reference)
#include <cuda_runtime.h>

// BoxBlur 13x13 reflect, (8,64,512,512) fp32. Separable, sliding-window.
// = R10 (conflict-free staging) with ONE trade: pass-2 ring (13 regs) replaced
//   by smem-reload slide -> regs ~25 <= 32 cap -> 4 CTAs/SM = 64 warps (was
//   reg-file-capped at 3 CTAs / 48 warps with 40 regs).

#define Wd 512
#define Hd 512
#define TY 16
#define NT 512
#define PW 513            // vs stride: banks (rl + 8seg + c) % 32 all distinct
#define OW 513            // os stride: conflict-free STS (R10)
#define KHALF 6

#define SMEM_FLOATS (TY * PW + 8 * OW)
#define SMEM_BYTES  (SMEM_FLOATS * 4)       // 49,248 B -> 4 CTAs/SM (197KB)

__device__ __forceinline__ int reflect_i(int i, int n) {
    // jnp.pad 'reflect', pad (6) < n: single fold.
    if (i < 0) i = -i;
    if (i >= n) i = 2 * n - 2 - i;
    return i;
}

__global__ __launch_bounds__(NT, 4)
void boxblur11(const float* __restrict__ in,
               const float* __restrict__ kern,
               float* __restrict__ out) {
    extern __shared__ float sm[];
    float* __restrict__ vs = sm;             // [TY][PW]  vertical 13-sums
    float* __restrict__ os = sm + TY * PW;   // [8][OW]   output staging

    const int ytile = blockIdx.x;
    const int plane = blockIdx.y;
    const int y0 = ytile * TY;
    const float* __restrict__ ip = in  + (size_t)plane * (Hd * Wd);
    float*       __restrict__ op = out + (size_t)plane * (Hd * Wd);
    const int t = threadIdx.x;               // 0..511
    const float k0 = kern[0];                // 1/169

    // ---- Pass 1: vertical running 13-sum, thread t = column t ----
    // (reload form; low regs. Outgoing-row re-read hits L1/L2.)
    {
        float s = 0.0f;
        #pragma unroll
        for (int j = -KHALF; j < KHALF; j++)           // 12 init rows
            s += ip[reflect_i(y0 + j, Hd) * Wd + t];
        #pragma unroll
        for (int j = 0; j < TY; j++) {
            s += ip[reflect_i(y0 + j + KHALF, Hd) * Wd + t];   // incoming
            vs[j * PW + t] = s;
            s -= ip[reflect_i(y0 + j - KHALF, Hd) * Wd + t];   // outgoing (cache hit)
        }
    }
    __syncthreads();

    // ---- Pass 2: horizontal sliding 13-sums, two 8-row halves, RING-FREE ----
    const int rl  = t & 7;          // local row within half
    const int seg = t >> 3;         // 0..63, 8-wide x segment
    const int xb  = seg * 8;
    const int g   = t & 127;        // flush: column lane
    const int r2  = t >> 7;         // flush: row base (0..3)

    #pragma unroll
    for (int h = 0; h < 2; h++) {
        const int row = h * 8 + rl;
        const float* __restrict__ vrow = vs + row * PW;

        float s = 0.0f;
        #pragma unroll
        for (int k = 0; k < 13; k++)
            s += vrow[reflect_i(xb - KHALF + k, Wd)];
        #pragma unroll
        for (int i = 0; i < 8; i++) {
            os[rl * OW + xb + i] = s * k0;          // conflict-free STS
            // slide: incoming x+7, outgoing x-6 (both conflict-free LDS)
            s += vrow[reflect_i(xb + i + KHALF + 1, Wd)]
               - vrow[reflect_i(xb + i - KHALF, Wd)];
        }
        __syncthreads();
        // flush half tile: scalar, lane map x = g + 128e
        // (LDS banks g%32 conflict-free; STG lanes consecutive -> coalesced)
        #pragma unroll
        for (int rr = 0; rr < 2; rr++) {
            const int rowf = r2 + rr * 4;
            float* __restrict__ od = op + (size_t)(y0 + h * 8 + rowf) * Wd;
            const float* __restrict__ osr = os + rowf * OW;
            #pragma unroll
            for (int e = 0; e < 4; e++) {
                od[g + 128 * e] = osr[g + 128 * e];
            }
        }
        __syncthreads();
    }
}

extern "C" void kernel_launch(void* const* d_in, const int* in_sizes, int n_in,
                              void* d_out, int out_size) {
    const float* input  = (const float*)d_in[0];   // (8,64,512,512) fp32
    const float* kernel = (const float*)d_in[1];   // (1,13,13) fp32 uniform
    float* out = (float*)d_out;

    cudaFuncSetAttribute(boxblur11, cudaFuncAttributeMaxDynamicSharedMemorySize,
                         SMEM_BYTES);

    dim3 grid(Hd / TY, 8 * 64);    // (32 y-tiles, 512 planes)
    boxblur11<<<grid, NT, SMEM_BYTES>>>(input, kernel, out);
}

// round 12
// speedup vs baseline: 1.1315x; 1.1315x over previous
#include <cuda_runtime.h>

// BoxBlur 13x13 reflect, (8,64,512,512) fp32. Separable, sliding-window.
// Warp-private pass 2: each of 16 warps owns a 32-column block for all 16
// rows — stages into its own os slice and flushes it (128B coalesced STG per
// row). ONE __syncthreads per CTA (after pass 1); pass-2/flush fully
// warp-independent -> phases decorrelate, DRAM stays fed.

#define Wd 512
#define Hd 512
#define TY 16
#define NT 512
#define PW 513            // vs stride (conflict-free)
#define OW 513            // os stride (conflict-free)
#define KHALF 6

#define SMEM_FLOATS (TY * PW + TY * OW)
#define SMEM_BYTES  (SMEM_FLOATS * 4)       // 65,664 B -> 3 CTAs/SM (197KB)

__device__ __forceinline__ int reflect_i(int i, int n) {
    // jnp.pad 'reflect', pad (6) < n: single fold.
    if (i < 0) i = -i;
    if (i >= n) i = 2 * n - 2 - i;
    return i;
}

__global__ __launch_bounds__(NT, 3)
void boxblur12(const float* __restrict__ in,
               const float* __restrict__ kern,
               float* __restrict__ out) {
    extern __shared__ float sm[];
    float* __restrict__ vs = sm;             // [TY][PW]  vertical 13-sums
    float* __restrict__ os = sm + TY * PW;   // [TY][OW]  output staging

    const int ytile = blockIdx.x;
    const int plane = blockIdx.y;
    const int y0 = ytile * TY;
    const float* __restrict__ ip = in  + (size_t)plane * (Hd * Wd);
    float*       __restrict__ op = out + (size_t)plane * (Hd * Wd);
    const int t = threadIdx.x;               // 0..511
    const float k0 = kern[0];                // 1/169

    // ---- Pass 1: vertical running 13-sum, thread t = column t ----
    // (reload form: outgoing-row re-read hits L1; 3 CTAs x 56KB = 168KB < L1)
    {
        float s = 0.0f;
        #pragma unroll
        for (int j = -KHALF; j < KHALF; j++)           // 12 init rows
            s += ip[reflect_i(y0 + j, Hd) * Wd + t];
        #pragma unroll
        for (int j = 0; j < TY; j++) {
            s += ip[reflect_i(y0 + j + KHALF, Hd) * Wd + t];   // incoming
            vs[j * PW + t] = s;
            s -= ip[reflect_i(y0 + j - KHALF, Hd) * Wd + t];   // outgoing (cache hit)
        }
    }
    __syncthreads();   // the ONLY block-wide sync

    // ---- Pass 2 + flush: warp-private 32-column block, all 16 rows ----
    {
        const int lane = t & 31;
        const int w    = t >> 5;        // warp 0..15: columns [32w, 32w+32)
        const int rl   = lane & 15;     // row 0..15
        const int sc   = lane >> 4;     // half-block select
        const int xb   = 32 * w + 16 * sc;
        const float* __restrict__ vrow = vs + rl * PW;
        float* __restrict__ orow = os + rl * OW;

        // ring-free sliding 13-sum over 16 outputs
        float s = 0.0f;
        #pragma unroll
        for (int k = 0; k < 13; k++)
            s += vrow[reflect_i(xb - KHALF + k, Wd)];
        #pragma unroll
        for (int i = 0; i < 16; i++) {
            orow[xb + i] = s * k0;      // STS banks (rl+16sc+i)%32: conflict-free
            s += vrow[reflect_i(xb + i + KHALF + 1, Wd)]
               - vrow[reflect_i(xb + i - KHALF, Wd)];
        }
        __syncwarp();

        // flush own 32-col block: lane = column -> 128B coalesced STG per row
        const int c = 32 * w + lane;
        #pragma unroll
        for (int row = 0; row < TY; row++) {
            op[(size_t)(y0 + row) * Wd + c] = os[row * OW + c];  // LDS banks (row+lane)%32
        }
    }
}

extern "C" void kernel_launch(void* const* d_in, const int* in_sizes, int n_in,
                              void* d_out, int out_size) {
    const float* input  = (const float*)d_in[0];   // (8,64,512,512) fp32
    const float* kernel = (const float*)d_in[1];   // (1,13,13) fp32 uniform
    float* out = (float*)d_out;

    cudaFuncSetAttribute(boxblur12, cudaFuncAttributeMaxDynamicSharedMemorySize,
                         SMEM_BYTES);

    dim3 grid(Hd / TY, 8 * 64);    // (32 y-tiles, 512 planes)
    boxblur12<<<grid, NT, SMEM_BYTES>>>(input, kernel, out);
}